// round 16
// baseline (speedup 1.0000x reference)
#include <cuda_runtime.h>
#include <cuda_bf16.h>
#include <cstdint>

#define Nn 8192
#define Dd 256
#define NSUB 16
#define PROW 1024             // padded rows per subject
#define PTOT (NSUB*PROW)      // 16384
#define GRID_MINE 152
#define GRID_LOSS 16

#define RB     144            // smem row stride bytes (LDSM conflict-free)
#define TILE_B 18432          // 128 rows * 144B
#define STG    36864          // bytes per K-chunk pair (A + B)
#define META   147456         // 4 chunk pairs (full K=256 resident)
#define SMEM_DYN (META + 8*128*4)

__device__ __align__(256) __nv_bfloat16 g_pe[PTOT*Dd];
__device__ float g_psq[PTOT];
__device__ int   g_plab[PTOT];
__device__ int   g_porg[PTOT];
__device__ int   g_cnt[NSUB];
__device__ int   g_done;
__device__ double g_sum;
__device__ int    g_vcnt;
__device__ unsigned long long g_bp[Nn+1];
__device__ unsigned long long g_bn[Nn+1];

// ---------------- PTX helpers ----------------
__device__ __forceinline__ uint32_t smem_u32(const void* p) {
    uint32_t a;
    asm("{ .reg .u64 t; cvta.to.shared.u64 t, %1; cvt.u32.u64 %0, t; }" : "=r"(a) : "l"(p));
    return a;
}
__device__ __forceinline__ void cpa16(uint32_t dst, const __nv_bfloat16* src) {
    asm volatile("cp.async.cg.shared.global [%0], [%1], 16;" :: "r"(dst), "l"(src));
}
__device__ __forceinline__ void cpa_commit() { asm volatile("cp.async.commit_group;" ::: "memory"); }
__device__ __forceinline__ void cpa_wait0()  { asm volatile("cp.async.wait_group 0;" ::: "memory"); }

__device__ __forceinline__ void ldsm4(uint32_t* r, uint32_t addr) {
    asm volatile("ldmatrix.sync.aligned.m8n8.x4.shared.b16 {%0,%1,%2,%3}, [%4];"
        : "=r"(r[0]), "=r"(r[1]), "=r"(r[2]), "=r"(r[3]) : "r"(addr));
}
__device__ __forceinline__ void mma16(float* c, const uint32_t* a, uint32_t b0, uint32_t b1) {
    asm volatile("mma.sync.aligned.m16n8k16.row.col.f32.bf16.bf16.f32 "
        "{%0,%1,%2,%3}, {%4,%5,%6,%7}, {%8,%9}, {%0,%1,%2,%3};"
        : "+f"(c[0]), "+f"(c[1]), "+f"(c[2]), "+f"(c[3])
        : "r"(a[0]), "r"(a[1]), "r"(a[2]), "r"(a[3]), "r"(b0), "r"(b1));
}

// ---------------- init: counters + meta pad defaults + best-key init ----------------
__global__ void init_k() {
    int t = blockIdx.x * blockDim.x + threadIdx.x;   // 64*256 = 16384 threads
    if (t == 0) { g_done = 0; g_sum = 0.0; g_vcnt = 0; }
    if (t < NSUB) g_cnt[t] = 0;
    if (t < PTOT) { g_plab[t] = -2; g_porg[t] = Nn; g_psq[t] = 0.f; }
    if (t <= Nn) { g_bp[t] = 0ull; g_bn[t] = ~0ull; }
}

// ---------------- gather: block-aggregated slot reservation + convert ----------------
__global__ __launch_bounds__(1024)
void gather_k(const float* __restrict__ emb, const int* __restrict__ labels,
              const int* __restrict__ sbj) {
    __shared__ int scnt[NSUB];
    __shared__ int sbase[NSUB];
    __shared__ int sgw[128];
    const int tid = threadIdx.x;
    const int b0  = blockIdx.x * 128;

    if (tid < NSUB) scnt[tid] = 0;
    __syncthreads();
    int s = 0, rank = 0;
    if (tid < 128) {
        s = sbj[b0 + tid];
        rank = atomicAdd(&scnt[s], 1);
    }
    __syncthreads();
    if (tid < NSUB && scnt[tid]) sbase[tid] = atomicAdd(&g_cnt[tid], scnt[tid]);
    __syncthreads();
    if (tid < 128) sgw[tid] = s * PROW + sbase[s] + rank;
    __syncthreads();

    const int wid = tid >> 5, lane = tid & 31;
    #pragma unroll
    for (int r = 0; r < 4; r++) {
        const int lr = wid * 4 + r;
        const int i  = b0 + lr;
        const int gw = sgw[lr];
        const float4* p = (const float4*)(emb + (size_t)i * Dd);
        float4 v0 = p[lane], v1 = p[lane + 32];
        float ssum = v0.x*v0.x + v0.y*v0.y + v0.z*v0.z + v0.w*v0.w
                   + v1.x*v1.x + v1.y*v1.y + v1.z*v1.z + v1.w*v1.w;
        #pragma unroll
        for (int o = 16; o; o >>= 1) ssum += __shfl_xor_sync(0xffffffffu, ssum, o);
        __nv_bfloat162* ph = (__nv_bfloat162*)(g_pe + (size_t)gw * Dd);
        ph[2*lane]        = __nv_bfloat162(__float2bfloat16_rn(v0.x), __float2bfloat16_rn(v0.y));
        ph[2*lane+1]      = __nv_bfloat162(__float2bfloat16_rn(v0.z), __float2bfloat16_rn(v0.w));
        ph[2*(lane+32)]   = __nv_bfloat162(__float2bfloat16_rn(v1.x), __float2bfloat16_rn(v1.y));
        ph[2*(lane+32)+1] = __nv_bfloat162(__float2bfloat16_rn(v1.z), __float2bfloat16_rn(v1.w));
        if (!lane) { g_psq[gw] = ssum; g_plab[gw] = labels[i]; g_porg[gw] = i; }
    }
}

// ---------------- chunk loader (skips B tile for diagonal) ----------------
__device__ __forceinline__ void prefetch(uint32_t stg32, int i0, int j0, int kk,
                                         int tid, bool diag) {
    #pragma unroll
    for (int t = 0; t < 4; t++) {          // A tile
        int w   = tid + t * 256;
        int row = w >> 3, k4 = w & 7;
        cpa16(stg32 + row * RB + k4 * 16,
              g_pe + (size_t)(i0 + row) * Dd + kk + k4 * 8);
    }
    if (!diag) {
        #pragma unroll
        for (int t = 0; t < 4; t++) {      // B tile
            int w   = tid + t * 256;
            int row = w >> 3, k4 = w & 7;
            cpa16(stg32 + TILE_B + row * RB + k4 * 16,
                  g_pe + (size_t)(j0 + row) * Dd + kk + k4 * 8);
        }
    }
}

// ---------------- fused within-subject distance GEMM + bidirectional mining ----------------
__global__ __launch_bounds__(256, 1)
void mine_k() {
    extern __shared__ __align__(16) char sb[];
    const uint32_t sb32 = smem_u32(sb);

    const int tid  = threadIdx.x;
    const int wid  = tid >> 5;
    const int lane = tid & 31;
    const int gr   = lane >> 2;
    const int gc   = lane & 3;
    const int wy   = wid >> 2;
    const int wx   = wid & 3;

    const uint32_t lrow = lane & 15, khalf = lane >> 4;
    const uint32_t aoff  = (wy * 64 + lrow) * RB + khalf * 16;
    const uint32_t boff0 = (wx * 32 + lrow) * RB + khalf * 16;

    int*   s_labi = (int*)  (sb + META);
    float* s_sqi  = (float*)(sb + META + 512);
    int*   s_orgi = (int*)  (sb + META + 1024);
    int*   s_labj = (int*)  (sb + META + 1536);
    float* s_sqj  = (float*)(sb + META + 2048);
    int*   s_orgj = (int*)  (sb + META + 2560);

    int off[NSUB + 1];
    off[0] = 0;
    #pragma unroll
    for (int s = 0; s < NSUB; s++) {
        int nt = (g_cnt[s] + 127) >> 7;
        off[s + 1] = off[s] + nt * (nt + 1) / 2;
    }
    const int total = off[NSUB];

    for (int u = blockIdx.x; u < total; u += GRID_MINE) {
        int s = 0;
        #pragma unroll
        for (int t = 0; t < NSUB; t++) if (u >= off[t + 1]) s = t + 1;
        const int nt = (g_cnt[s] + 127) >> 7;
        int l = u - off[s];
        int ti = 0;
        #pragma unroll
        for (int t = 0; t < 8; t++) { if (l >= nt - ti) { l -= nt - ti; ti++; } }
        const int tj = ti + l;
        const int i0 = s * PROW + ti * 128;
        const int j0 = s * PROW + tj * 128;
        const bool diag = (ti == tj);
        const uint32_t btile = diag ? 0u : (uint32_t)TILE_B;

        __syncthreads();   // previous iteration done reading smem
        if (tid < 128) {
            s_labi[tid] = g_plab[i0 + tid];
            s_sqi[tid]  = g_psq[i0 + tid];
            s_orgi[tid] = g_porg[i0 + tid];
            s_labj[tid] = g_plab[j0 + tid];
            s_sqj[tid]  = g_psq[j0 + tid];
            s_orgj[tid] = g_porg[j0 + tid];
        }

        // single-shot: load ALL of K=256 for A and B, one wait, one sync
        #pragma unroll
        for (int c = 0; c < 4; c++)
            prefetch(sb32 + c * STG, i0, j0, c * 64, tid, diag);
        cpa_commit();
        cpa_wait0();
        __syncthreads();

        float acc[4][4][4];
        #pragma unroll
        for (int mt = 0; mt < 4; mt++)
            #pragma unroll
            for (int nt2 = 0; nt2 < 4; nt2++)
                #pragma unroll
                for (int q = 0; q < 4; q++) acc[mt][nt2][q] = 0.f;

        #pragma unroll
        for (int c = 0; c < 4; c++) {
            const uint32_t stb = sb32 + c * STG;
            #pragma unroll
            for (int ks = 0; ks < 4; ks++) {
                const uint32_t kb = ks * 32;
                uint32_t B0[4], B1[4];
                ldsm4(B0, stb + btile + boff0 + kb);
                ldsm4(B1, stb + btile + boff0 + 16 * RB + kb);
                #pragma unroll
                for (int mt = 0; mt < 4; mt++) {
                    uint32_t ah[4];
                    ldsm4(ah, stb + aoff + mt * 16 * RB + kb);
                    mma16(acc[mt][0], ah, B0[0], B0[2]);
                    mma16(acc[mt][1], ah, B0[1], B0[3]);
                    mma16(acc[mt][2], ah, B1[0], B1[2]);
                    mma16(acc[mt][3], ah, B1[1], B1[3]);
                }
            }
        }

        // ---------- attribute caches ----------
        float sqjv[8]; int labj[8], jg[8];
        #pragma unroll
        for (int q = 0; q < 8; q++) {
            int cl = wx * 32 + (q >> 1) * 8 + 2 * gc + (q & 1);
            sqjv[q] = s_sqj[cl]; labj[q] = s_labj[cl]; jg[q] = s_orgj[cl];
        }
        float sqiv[8]; int labi[8], igr[8];
        #pragma unroll
        for (int r = 0; r < 8; r++) {
            int rl = wy * 64 + (r >> 1) * 16 + gr + (r & 1) * 8;
            sqiv[r] = s_sqi[rl]; labi[r] = s_labi[rl]; igr[r] = s_orgi[rl];
        }

        // ---------- transform acc -> clamped d^2 ----------
        #pragma unroll
        for (int mt = 0; mt < 4; mt++)
            #pragma unroll
            for (int nt2 = 0; nt2 < 4; nt2++)
                #pragma unroll
                for (int q = 0; q < 4; q++)
                    acc[mt][nt2][q] = fmaxf(fmaf(-2.f, acc[mt][nt2][q],
                        sqiv[mt * 2 + (q >> 1)] + sqjv[nt2 * 2 + (q & 1)]), 0.f);

        // ---------- row mining ----------
        #pragma unroll
        for (int r = 0; r < 8; r++) {
            float bpd = -1.f;    int bpi = -1;
            float bnd = 3.4e38f; int bni = -1;
            const bool ra = (labi[r] >= 0);
            #pragma unroll
            for (int q = 0; q < 8; q++) {
                float d2 = acc[r >> 1][q >> 1][(r & 1) * 2 + (q & 1)];
                if (labj[q] == labi[r]) {
                    if (jg[q] != igr[r] && d2 > bpd) { bpd = d2; bpi = jg[q]; }
                } else if (ra && labj[q] >= 0) {
                    if (d2 < bnd) { bnd = d2; bni = jg[q]; }
                }
            }
            #pragma unroll
            for (int o = 1; o < 4; o <<= 1) {
                float od = __shfl_xor_sync(0xffffffffu, bpd, o);
                int   oi = __shfl_xor_sync(0xffffffffu, bpi, o);
                if (oi >= 0 && (bpi < 0 || od > bpd || (od == bpd && oi < bpi))) { bpd = od; bpi = oi; }
                od = __shfl_xor_sync(0xffffffffu, bnd, o);
                oi = __shfl_xor_sync(0xffffffffu, bni, o);
                if (oi >= 0 && (bni < 0 || od < bnd || (od == bnd && oi < bni))) { bnd = od; bni = oi; }
            }
            if (gc == 0) {
                if (bpi >= 0)
                    atomicMax(&g_bp[igr[r]], ((unsigned long long)__float_as_uint(bpd) << 32) |
                                             (unsigned long long)(~(unsigned)bpi));
                if (bni >= 0)
                    atomicMin(&g_bn[igr[r]], ((unsigned long long)__float_as_uint(bnd) << 32) |
                                             (unsigned long long)(unsigned)bni);
            }
        }

        // ---------- column mining (transpose view; skip diagonal) ----------
        if (!diag) {
            #pragma unroll
            for (int q = 0; q < 8; q++) {
                float bpd = -1.f;    int bpi = -1;
                float bnd = 3.4e38f; int bni = -1;
                const bool ca = (labj[q] >= 0);
                #pragma unroll
                for (int r = 0; r < 8; r++) {
                    float d2 = acc[r >> 1][q >> 1][(r & 1) * 2 + (q & 1)];
                    if (labi[r] == labj[q]) {
                        if (igr[r] != jg[q] && d2 > bpd) { bpd = d2; bpi = igr[r]; }
                    } else if (ca && labi[r] >= 0) {
                        if (d2 < bnd) { bnd = d2; bni = igr[r]; }
                    }
                }
                #pragma unroll
                for (int o = 4; o < 32; o <<= 1) {
                    float od = __shfl_xor_sync(0xffffffffu, bpd, o);
                    int   oi = __shfl_xor_sync(0xffffffffu, bpi, o);
                    if (oi >= 0 && (bpi < 0 || od > bpd || (od == bpd && oi < bpi))) { bpd = od; bpi = oi; }
                    od = __shfl_xor_sync(0xffffffffu, bnd, o);
                    oi = __shfl_xor_sync(0xffffffffu, bni, o);
                    if (oi >= 0 && (bni < 0 || od < bnd || (od == bnd && oi < bni))) { bnd = od; bni = oi; }
                }
                if (gr == 0) {
                    if (bpi >= 0)
                        atomicMax(&g_bp[jg[q]], ((unsigned long long)__float_as_uint(bpd) << 32) |
                                                (unsigned long long)(~(unsigned)bpi));
                    if (bni >= 0)
                        atomicMin(&g_bn[jg[q]], ((unsigned long long)__float_as_uint(bnd) << 32) |
                                                (unsigned long long)(unsigned)bni);
                }
            }
        }
    }
}

// ---------------- loss: 16 blocks, partial atomics, last block finalizes ----------------
__global__ void loss_k(float* __restrict__ out) {
    __shared__ float ssum[8];
    __shared__ int   scnt[8];
    __shared__ int   slast;
    const int tid = threadIdx.x;
    const int base = blockIdx.x * (Nn / GRID_LOSS);
    float acc = 0.f; int c = 0;
    for (int k = tid; k < Nn / GRID_LOSS; k += 256) {
        int i = base + k;
        unsigned long long pp = g_bp[i], pn = g_bn[i];
        if (pp != 0ull && pn != ~0ull) {
            float dp = sqrtf(__uint_as_float((unsigned)(pp >> 32)));
            float dn = sqrtf(__uint_as_float((unsigned)(pn >> 32)));
            acc += fmaxf(dp - dn + 1.0f, 0.f);
            c++;
        }
    }
    #pragma unroll
    for (int o = 16; o; o >>= 1) {
        acc += __shfl_xor_sync(0xffffffffu, acc, o);
        c   += __shfl_xor_sync(0xffffffffu, c, o);
    }
    if ((tid & 31) == 0) { ssum[tid >> 5] = acc; scnt[tid >> 5] = c; }
    __syncthreads();
    if (tid == 0) {
        float a = 0.f; int cc = 0;
        #pragma unroll
        for (int w = 0; w < 8; w++) { a += ssum[w]; cc += scnt[w]; }
        atomicAdd(&g_sum, (double)a);
        atomicAdd(&g_vcnt, cc);
        __threadfence();
        slast = (atomicAdd(&g_done, 1) == GRID_LOSS - 1) ? 1 : 0;
    }
    __syncthreads();
    if (tid == 0 && slast) {
        double s = atomicAdd(&g_sum, 0.0);
        int cc = atomicAdd(&g_vcnt, 0);
        out[0] = (float)(s / (double)(cc > 1 ? cc : 1));
    }
}

extern "C" void kernel_launch(void* const* d_in, const int* in_sizes, int n_in,
                              void* d_out, int out_size) {
    const float* emb    = (const float*)d_in[0];
    const int*   labels = (const int*)d_in[1];
    const int*   sbjv   = (const int*)d_in[2];
    float* out = (float*)d_out;

    cudaFuncSetAttribute(mine_k, cudaFuncAttributeMaxDynamicSharedMemorySize, SMEM_DYN);

    init_k<<<64, 256>>>();
    gather_k<<<64, 1024>>>(emb, labels, sbjv);
    mine_k<<<GRID_MINE, 256, SMEM_DYN>>>();
    loss_k<<<GRID_LOSS, 256>>>(out);
}

// round 17
// speedup vs baseline: 1.2797x; 1.2797x over previous
#include <cuda_runtime.h>
#include <cuda_bf16.h>
#include <cstdint>

#define Nn 8192
#define Dd 256
#define NSUB 16
#define PROW 1024             // padded rows per subject
#define PTOT (NSUB*PROW)      // 16384
#define GRID_MINE 288
#define NCH 4                 // K chunks of 64 elements
#define GRID_LOSS 16

#define RB     144            // smem row stride bytes (LDSM conflict-free)
#define TILE_B 18432          // 128 rows * 144B
#define STG    36864          // bytes per pipeline stage (A + B)
#define META   73728
#define SMEM_DYN (META + 8*128*4)

// ALL state is zero-initialized at module load and restored to zero by loss_k:
//   g_pe pad rows: never written, always 0 (masked by lab==0 guards)
//   g_plab: label+1 (0 = pad/invalid)   g_porg: orig+1 (0 = pad)
//   g_bp: 0 = invalid; key = d2bits<<32 | ~(org') via atomicMax
//   g_bn: 0 = invalid; stores ~(d2bits<<32 | org') via atomicMax (== min over key)
__device__ __align__(256) __nv_bfloat16 g_pe[PTOT*Dd];
__device__ float g_psq[PTOT];
__device__ int   g_plab[PTOT];
__device__ int   g_porg[PTOT];
__device__ int   g_cnt[NSUB];
__device__ int   g_done;
__device__ double g_sum;
__device__ int    g_vcnt;
__device__ unsigned long long g_bp[Nn];
__device__ unsigned long long g_bn[Nn];

// ---------------- PTX helpers ----------------
__device__ __forceinline__ uint32_t smem_u32(const void* p) {
    uint32_t a;
    asm("{ .reg .u64 t; cvta.to.shared.u64 t, %1; cvt.u32.u64 %0, t; }" : "=r"(a) : "l"(p));
    return a;
}
__device__ __forceinline__ void cpa16(uint32_t dst, const __nv_bfloat16* src) {
    asm volatile("cp.async.cg.shared.global [%0], [%1], 16;" :: "r"(dst), "l"(src));
}
__device__ __forceinline__ void cpa_commit() { asm volatile("cp.async.commit_group;" ::: "memory"); }
__device__ __forceinline__ void cpa_wait1()  { asm volatile("cp.async.wait_group 1;" ::: "memory"); }
__device__ __forceinline__ void cpa_wait0()  { asm volatile("cp.async.wait_group 0;" ::: "memory"); }

__device__ __forceinline__ void ldsm4(uint32_t* r, uint32_t addr) {
    asm volatile("ldmatrix.sync.aligned.m8n8.x4.shared.b16 {%0,%1,%2,%3}, [%4];"
        : "=r"(r[0]), "=r"(r[1]), "=r"(r[2]), "=r"(r[3]) : "r"(addr));
}
__device__ __forceinline__ void mma16(float* c, const uint32_t* a, uint32_t b0, uint32_t b1) {
    asm volatile("mma.sync.aligned.m16n8k16.row.col.f32.bf16.bf16.f32 "
        "{%0,%1,%2,%3}, {%4,%5,%6,%7}, {%8,%9}, {%0,%1,%2,%3};"
        : "+f"(c[0]), "+f"(c[1]), "+f"(c[2]), "+f"(c[3])
        : "r"(a[0]), "r"(a[1]), "r"(a[2]), "r"(a[3]), "r"(b0), "r"(b1));
}

// ---------------- gather: block-aggregated slot reservation + convert ----------------
__global__ __launch_bounds__(1024)
void gather_k(const float* __restrict__ emb, const int* __restrict__ labels,
              const int* __restrict__ sbj) {
    __shared__ int scnt[NSUB];
    __shared__ int sbase[NSUB];
    __shared__ int sgw[128];
    const int tid = threadIdx.x;
    const int b0  = blockIdx.x * 128;

    if (tid < NSUB) scnt[tid] = 0;
    __syncthreads();
    int s = 0, rank = 0;
    if (tid < 128) {
        s = sbj[b0 + tid];
        rank = atomicAdd(&scnt[s], 1);
    }
    __syncthreads();
    if (tid < NSUB && scnt[tid]) sbase[tid] = atomicAdd(&g_cnt[tid], scnt[tid]);
    __syncthreads();
    if (tid < 128) sgw[tid] = s * PROW + sbase[s] + rank;
    __syncthreads();

    const int wid = tid >> 5, lane = tid & 31;
    #pragma unroll
    for (int r = 0; r < 4; r++) {
        const int lr = wid * 4 + r;
        const int i  = b0 + lr;
        const int gw = sgw[lr];
        const float4* p = (const float4*)(emb + (size_t)i * Dd);
        float4 v0 = p[lane], v1 = p[lane + 32];
        float ssum = v0.x*v0.x + v0.y*v0.y + v0.z*v0.z + v0.w*v0.w
                   + v1.x*v1.x + v1.y*v1.y + v1.z*v1.z + v1.w*v1.w;
        #pragma unroll
        for (int o = 16; o; o >>= 1) ssum += __shfl_xor_sync(0xffffffffu, ssum, o);
        __nv_bfloat162* ph = (__nv_bfloat162*)(g_pe + (size_t)gw * Dd);
        ph[2*lane]        = __nv_bfloat162(__float2bfloat16_rn(v0.x), __float2bfloat16_rn(v0.y));
        ph[2*lane+1]      = __nv_bfloat162(__float2bfloat16_rn(v0.z), __float2bfloat16_rn(v0.w));
        ph[2*(lane+32)]   = __nv_bfloat162(__float2bfloat16_rn(v1.x), __float2bfloat16_rn(v1.y));
        ph[2*(lane+32)+1] = __nv_bfloat162(__float2bfloat16_rn(v1.z), __float2bfloat16_rn(v1.w));
        if (!lane) { g_psq[gw] = ssum; g_plab[gw] = labels[i] + 1; g_porg[gw] = i + 1; }
    }
}

// ---------------- chunk loader (skips B tile for diagonal) ----------------
__device__ __forceinline__ void prefetch(uint32_t stg32, int i0, int j0, int kk,
                                         int tid, bool diag) {
    #pragma unroll
    for (int t = 0; t < 4; t++) {          // A tile
        int w   = tid + t * 256;
        int row = w >> 3, k4 = w & 7;
        cpa16(stg32 + row * RB + k4 * 16,
              g_pe + (size_t)(i0 + row) * Dd + kk + k4 * 8);
    }
    if (!diag) {
        #pragma unroll
        for (int t = 0; t < 4; t++) {      // B tile
            int w   = tid + t * 256;
            int row = w >> 3, k4 = w & 7;
            cpa16(stg32 + TILE_B + row * RB + k4 * 16,
                  g_pe + (size_t)(j0 + row) * Dd + kk + k4 * 8);
        }
    }
}

// ---------------- fused within-subject distance GEMM + bidirectional mining ----------------
__global__ __launch_bounds__(256, 2)
void mine_k() {
    extern __shared__ __align__(16) char sb[];
    const uint32_t sb32 = smem_u32(sb);

    const int tid  = threadIdx.x;
    const int wid  = tid >> 5;
    const int lane = tid & 31;
    const int gr   = lane >> 2;
    const int gc   = lane & 3;
    const int wy   = wid >> 2;
    const int wx   = wid & 3;

    const uint32_t lrow = lane & 15, khalf = lane >> 4;
    const uint32_t aoff  = (wy * 64 + lrow) * RB + khalf * 16;
    const uint32_t boff0 = (wx * 32 + lrow) * RB + khalf * 16;

    int*   s_labi = (int*)  (sb + META);
    float* s_sqi  = (float*)(sb + META + 512);
    int*   s_orgi = (int*)  (sb + META + 1024);
    int*   s_labj = (int*)  (sb + META + 1536);
    float* s_sqj  = (float*)(sb + META + 2048);
    int*   s_orgj = (int*)  (sb + META + 2560);

    int off[NSUB + 1];
    off[0] = 0;
    #pragma unroll
    for (int s = 0; s < NSUB; s++) {
        int nt = (g_cnt[s] + 127) >> 7;
        off[s + 1] = off[s] + nt * (nt + 1) / 2;
    }
    const int total = off[NSUB];

    for (int u = blockIdx.x; u < total; u += GRID_MINE) {
        int s = 0;
        #pragma unroll
        for (int t = 0; t < NSUB; t++) if (u >= off[t + 1]) s = t + 1;
        const int nt = (g_cnt[s] + 127) >> 7;
        int l = u - off[s];
        int ti = 0;
        #pragma unroll
        for (int t = 0; t < 8; t++) { if (l >= nt - ti) { l -= nt - ti; ti++; } }
        const int tj = ti + l;
        const int i0 = s * PROW + ti * 128;
        const int j0 = s * PROW + tj * 128;
        const bool diag = (ti == tj);
        const uint32_t btile = diag ? 0u : (uint32_t)TILE_B;

        __syncthreads();   // previous epilogue done reading meta
        if (tid < 128) {
            s_labi[tid] = g_plab[i0 + tid];
            s_sqi[tid]  = g_psq[i0 + tid];
            s_orgi[tid] = g_porg[i0 + tid];
            s_labj[tid] = g_plab[j0 + tid];
            s_sqj[tid]  = g_psq[j0 + tid];
            s_orgj[tid] = g_porg[j0 + tid];
        }

        prefetch(sb32,       i0, j0,  0, tid, diag); cpa_commit();
        prefetch(sb32 + STG, i0, j0, 64, tid, diag); cpa_commit();

        float acc[4][4][4];
        #pragma unroll
        for (int mt = 0; mt < 4; mt++)
            #pragma unroll
            for (int nt2 = 0; nt2 < 4; nt2++)
                #pragma unroll
                for (int q = 0; q < 4; q++) acc[mt][nt2][q] = 0.f;

        for (int c = 0; c < NCH; c++) {
            const int st = c & 1;
            if (c < NCH - 1) cpa_wait1(); else cpa_wait0();
            __syncthreads();

            const uint32_t stb = sb32 + st * STG;
            #pragma unroll
            for (int ks = 0; ks < 4; ks++) {
                const uint32_t kb = ks * 32;
                uint32_t B0[4], B1[4];
                ldsm4(B0, stb + btile + boff0 + kb);
                ldsm4(B1, stb + btile + boff0 + 16 * RB + kb);
                #pragma unroll
                for (int mt = 0; mt < 4; mt++) {
                    uint32_t ah[4];
                    ldsm4(ah, stb + aoff + mt * 16 * RB + kb);
                    mma16(acc[mt][0], ah, B0[0], B0[2]);
                    mma16(acc[mt][1], ah, B0[1], B0[3]);
                    mma16(acc[mt][2], ah, B1[0], B1[2]);
                    mma16(acc[mt][3], ah, B1[1], B1[3]);
                }
            }
            __syncthreads();
            if (c + 2 < NCH) {
                prefetch(sb32 + st * STG, i0, j0, (c + 2) * 64, tid, diag);
                cpa_commit();
            }
        }

        // ---------- attribute caches (lab' = lab+1, org' = orig+1; 0 = pad) ----------
        float sqjv[8]; int labj[8], jg[8];
        #pragma unroll
        for (int q = 0; q < 8; q++) {
            int cl = wx * 32 + (q >> 1) * 8 + 2 * gc + (q & 1);
            sqjv[q] = s_sqj[cl]; labj[q] = s_labj[cl]; jg[q] = s_orgj[cl];
        }
        float sqiv[8]; int labi[8], igr[8];
        #pragma unroll
        for (int r = 0; r < 8; r++) {
            int rl = wy * 64 + (r >> 1) * 16 + gr + (r & 1) * 8;
            sqiv[r] = s_sqi[rl]; labi[r] = s_labi[rl]; igr[r] = s_orgi[rl];
        }

        // ---------- transform acc -> clamped d^2 ----------
        #pragma unroll
        for (int mt = 0; mt < 4; mt++)
            #pragma unroll
            for (int nt2 = 0; nt2 < 4; nt2++)
                #pragma unroll
                for (int q = 0; q < 4; q++)
                    acc[mt][nt2][q] = fmaxf(fmaf(-2.f, acc[mt][nt2][q],
                        sqiv[mt * 2 + (q >> 1)] + sqjv[nt2 * 2 + (q & 1)]), 0.f);

        // ---------- row mining ----------
        #pragma unroll
        for (int r = 0; r < 8; r++) {
            float bpd = -1.f;    int bpi = -1;
            float bnd = 3.4e38f; int bni = -1;
            const bool ra = (labi[r] > 0);
            #pragma unroll
            for (int q = 0; q < 8; q++) {
                float d2 = acc[r >> 1][q >> 1][(r & 1) * 2 + (q & 1)];
                if (labj[q] == labi[r]) {
                    if (jg[q] != igr[r] && d2 > bpd) { bpd = d2; bpi = jg[q]; }
                } else if (ra && labj[q] > 0) {
                    if (d2 < bnd) { bnd = d2; bni = jg[q]; }
                }
            }
            #pragma unroll
            for (int o = 1; o < 4; o <<= 1) {
                float od = __shfl_xor_sync(0xffffffffu, bpd, o);
                int   oi = __shfl_xor_sync(0xffffffffu, bpi, o);
                if (oi >= 0 && (bpi < 0 || od > bpd || (od == bpd && oi < bpi))) { bpd = od; bpi = oi; }
                od = __shfl_xor_sync(0xffffffffu, bnd, o);
                oi = __shfl_xor_sync(0xffffffffu, bni, o);
                if (oi >= 0 && (bni < 0 || od < bnd || (od == bnd && oi < bni))) { bnd = od; bni = oi; }
            }
            if (gc == 0 && ra) {
                if (bpi >= 0)
                    atomicMax(&g_bp[igr[r] - 1], ((unsigned long long)__float_as_uint(bpd) << 32) |
                                                 (unsigned long long)(~(unsigned)bpi));
                if (bni >= 0)
                    atomicMax(&g_bn[igr[r] - 1], ~(((unsigned long long)__float_as_uint(bnd) << 32) |
                                                   (unsigned long long)(unsigned)bni));
            }
        }

        // ---------- column mining (transpose view; skip diagonal) ----------
        if (!diag) {
            #pragma unroll
            for (int q = 0; q < 8; q++) {
                float bpd = -1.f;    int bpi = -1;
                float bnd = 3.4e38f; int bni = -1;
                const bool ca = (labj[q] > 0);
                #pragma unroll
                for (int r = 0; r < 8; r++) {
                    float d2 = acc[r >> 1][q >> 1][(r & 1) * 2 + (q & 1)];
                    if (labi[r] == labj[q]) {
                        if (igr[r] != jg[q] && d2 > bpd) { bpd = d2; bpi = igr[r]; }
                    } else if (ca && labi[r] > 0) {
                        if (d2 < bnd) { bnd = d2; bni = igr[r]; }
                    }
                }
                #pragma unroll
                for (int o = 4; o < 32; o <<= 1) {
                    float od = __shfl_xor_sync(0xffffffffu, bpd, o);
                    int   oi = __shfl_xor_sync(0xffffffffu, bpi, o);
                    if (oi >= 0 && (bpi < 0 || od > bpd || (od == bpd && oi < bpi))) { bpd = od; bpi = oi; }
                    od = __shfl_xor_sync(0xffffffffu, bnd, o);
                    oi = __shfl_xor_sync(0xffffffffu, bni, o);
                    if (oi >= 0 && (bni < 0 || od < bnd || (od == bnd && oi < bni))) { bnd = od; bni = oi; }
                }
                if (gr == 0 && ca) {
                    if (bpi >= 0)
                        atomicMax(&g_bp[jg[q] - 1], ((unsigned long long)__float_as_uint(bpd) << 32) |
                                                    (unsigned long long)(~(unsigned)bpi));
                    if (bni >= 0)
                        atomicMax(&g_bn[jg[q] - 1], ~(((unsigned long long)__float_as_uint(bnd) << 32) |
                                                      (unsigned long long)(unsigned)bni));
                }
            }
        }
    }
}

// ---------------- loss: consumes keys, RESTORES zero state, last block finalizes ----------------
__global__ void loss_k(float* __restrict__ out) {
    __shared__ float ssum[8];
    __shared__ int   scnt[8];
    __shared__ int   slast;
    const int tid = threadIdx.x;
    const int base = blockIdx.x * (Nn / GRID_LOSS);
    if (blockIdx.x == 0 && tid < NSUB) g_cnt[tid] = 0;   // mine_k is done with counts
    float acc = 0.f; int c = 0;
    for (int k = tid; k < Nn / GRID_LOSS; k += 256) {
        int i = base + k;
        unsigned long long pp = g_bp[i], mn = g_bn[i];
        if (pp != 0ull && mn != 0ull) {
            unsigned long long kn = ~mn;
            float dp = sqrtf(__uint_as_float((unsigned)(pp >> 32)));
            float dn = sqrtf(__uint_as_float((unsigned)(kn >> 32)));
            acc += fmaxf(dp - dn + 1.0f, 0.f);
            c++;
        }
        g_bp[i] = 0ull;   // restore zero state for next replay
        g_bn[i] = 0ull;
    }
    #pragma unroll
    for (int o = 16; o; o >>= 1) {
        acc += __shfl_xor_sync(0xffffffffu, acc, o);
        c   += __shfl_xor_sync(0xffffffffu, c, o);
    }
    if ((tid & 31) == 0) { ssum[tid >> 5] = acc; scnt[tid >> 5] = c; }
    __syncthreads();
    if (tid == 0) {
        float a = 0.f; int cc = 0;
        #pragma unroll
        for (int w = 0; w < 8; w++) { a += ssum[w]; cc += scnt[w]; }
        atomicAdd(&g_sum, (double)a);
        atomicAdd(&g_vcnt, cc);
        __threadfence();
        slast = (atomicAdd(&g_done, 1) == GRID_LOSS - 1) ? 1 : 0;
    }
    __syncthreads();
    if (tid == 0 && slast) {
        double s = atomicAdd(&g_sum, 0.0);
        int cc = atomicAdd(&g_vcnt, 0);
        out[0] = (float)(s / (double)(cc > 1 ? cc : 1));
        g_sum = 0.0; g_vcnt = 0; g_done = 0;             // restore zero state
    }
}

extern "C" void kernel_launch(void* const* d_in, const int* in_sizes, int n_in,
                              void* d_out, int out_size) {
    const float* emb    = (const float*)d_in[0];
    const int*   labels = (const int*)d_in[1];
    const int*   sbjv   = (const int*)d_in[2];
    float* out = (float*)d_out;

    cudaFuncSetAttribute(mine_k, cudaFuncAttributeMaxDynamicSharedMemorySize, SMEM_DYN);

    gather_k<<<64, 1024>>>(emb, labels, sbjv);
    mine_k<<<GRID_MINE, 256, SMEM_DYN>>>();
    loss_k<<<GRID_LOSS, 256>>>(out);
}